// round 14
// baseline (speedup 1.0000x reference)
#include <cuda_runtime.h>
#include <cuda_fp16.h>
#include <cstdint>
#include <math.h>

#define BATCH 4096
#define DM    768
#define NT    124
#define NRT   10240

__constant__ int c_shift[5] = {9, 8, 7, 6, 5};
__constant__ int c_tbase[5] = {0, 4, 12, 28, 60};
__constant__ int c_n[5]     = {4, 8, 16, 32, 64};
__constant__ unsigned long long c_goff[5] = {3145730ull, 3162114ull, 3194882ull, 3260418ull, 3391490ull};

#define SP_OFF  3145728ull
#define ACT_OFF 3145729ull

// ---- static device scratch ----
__device__ __align__(256) __half g_Xh[(size_t)BATCH * DM];
__device__ __align__(256) __half g_Vh[(size_t)NRT * DM];    // [10240][768]
__device__ __align__(256) __half g_W2h[(size_t)DM * NRT];   // [768][10240]
__device__ __align__(256) __half g_Yh[(size_t)BATCH * NRT];
__device__ __align__(256) __half g_ENCh[128 * DM];          // 124 rows + 4 zero rows
__device__ __align__(256) float g_P[4ull * BATCH * DM];
__device__ float g_BIAS[NT];
__device__ __align__(16) float g_GATE[(size_t)BATCH * 128];
__device__ float g_PSQV[320];
__device__ float g_PSQU[320];
__device__ float g_PSABS[32 * 128];
__device__ float g_PCNT[32 * 128];

struct P5 { const float* p[5]; };

__device__ __forceinline__ void decode_t(int t, int& g, int& tl) {
    if (t < 4)       { g = 0; tl = t; }
    else if (t < 12) { g = 1; tl = t - 4; }
    else if (t < 28) { g = 2; tl = t - 12; }
    else if (t < 60) { g = 3; tl = t - 28; }
    else             { g = 4; tl = t - 60; }
}

__device__ __forceinline__ float blk_reduce256(float v) {
    __shared__ float sh[256];
    int tid = threadIdx.x;
    sh[tid] = v;
    __syncthreads();
    for (int s = 128; s > 0; s >>= 1) {
        if (tid < s) sh[tid] += sh[tid + s];
        __syncthreads();
    }
    float r = sh[0];
    __syncthreads();
    return r;
}

// ---- PTX helpers (baseline sm_80+ PTX only) ----
__device__ __forceinline__ uint32_t smem_u32(const void* p) {
    uint32_t a;
    asm("{ .reg .u64 t; cvta.to.shared.u64 t, %1; cvt.u32.u64 %0, t; }" : "=r"(a) : "l"(p));
    return a;
}
__device__ __forceinline__ void cp16(uint32_t dst, const void* src) {
    asm volatile("cp.async.cg.shared.global [%0], [%1], 16;" :: "r"(dst), "l"(src) : "memory");
}
__device__ __forceinline__ void mma_f16(float* d, const uint32_t* a, const uint32_t* b) {
    asm volatile("mma.sync.aligned.m16n8k16.row.col.f32.f16.f16.f32 "
        "{%0,%1,%2,%3}, {%4,%5,%6,%7}, {%8,%9}, {%0,%1,%2,%3};"
        : "+f"(d[0]), "+f"(d[1]), "+f"(d[2]), "+f"(d[3])
        : "r"(a[0]), "r"(a[1]), "r"(a[2]), "r"(a[3]), "r"(b[0]), "r"(b[1]));
}
__device__ __forceinline__ void ldsm_x4(uint32_t& r0, uint32_t& r1, uint32_t& r2, uint32_t& r3,
                                        uint32_t addr) {
    asm volatile("ldmatrix.sync.aligned.m8n8.x4.shared.b16 {%0,%1,%2,%3}, [%4];"
        : "=r"(r0), "=r"(r1), "=r"(r2), "=r"(r3) : "r"(addr));
}

// ============== prep kernels ==============
__global__ void prep_fused(P5 V, P5 E, P5 Bv) {
    int b = blockIdx.x;
    if (b < 7680) {
        int i4 = b * 256 + threadIdx.x;                // < 1966080
        int n = i4 / 192, kq = i4 % 192;
        int g = n >> 11, lr = n & 2047;
        float4 v = ((const float4*)V.p[g])[(size_t)lr * 192 + kq];
        __half2 h0 = __floats2half2_rn(v.x, v.y);
        __half2 h1 = __floats2half2_rn(v.z, v.w);
        uint2 r; r.x = *(uint32_t*)&h0; r.y = *(uint32_t*)&h1;
        ((uint2*)g_Vh)[(size_t)n * 192 + kq] = r;
    } else {
        int t = b - 7680;                              // 0..127
        if (t < NT) {
            int g, tl; decode_t(t, g, tl);
            const float* src = E.p[g] + (size_t)tl * DM;
            for (int i = threadIdx.x; i < DM; i += blockDim.x)
                g_ENCh[t * DM + i] = __float2half_rn(src[i]);
            if (threadIdx.x == 0) g_BIAS[t] = Bv.p[g][tl];
        } else {
            for (int i = threadIdx.x; i < DM; i += blockDim.x)
                g_ENCh[t * DM + i] = __float2half_rn(0.f);
        }
    }
}

__global__ void rnd_x(const float* __restrict__ X) {
    int i4 = blockIdx.x * 256 + threadIdx.x;           // < 786432
    float4 v = ((const float4*)X)[i4];
    __half2 h0 = __floats2half2_rn(v.x, v.y);
    __half2 h1 = __floats2half2_rn(v.z, v.w);
    uint2 r; r.x = *(uint32_t*)&h0; r.y = *(uint32_t*)&h1;
    ((uint2*)g_Xh)[i4] = r;
}

__global__ void build_w2(P5 U) {
    int g = blockIdx.y;
    int r = 512 >> g;
    int rq = r >> 2;
    int i4 = blockIdx.x * 256 + threadIdx.x;           // < 393216 per group
    int t = i4 / (DM * rq);
    int rem = i4 % (DM * rq);
    int d = rem / rq, jq = rem % rq;
    float4 v = ((const float4*)U.p[g])[(size_t)(t * DM + d) * rq + jq];
    __half2 h0 = __floats2half2_rn(v.x, v.y);
    __half2 h1 = __floats2half2_rn(v.z, v.w);
    uint2 rv; rv.x = *(uint32_t*)&h0; rv.y = *(uint32_t*)&h1;
    ((uint2*)g_W2h)[(size_t)d * 2560 + (g << 9) + t * rq + jq] = rv;
}

// ============== balanced norms: 320 segments of 32 rows ==============
__global__ void norms2(P5 V, P5 U) {
    int s = blockIdx.x;                   // 0..319
    int g = s >> 6, idx = s & 63;
    int nseg = 16 >> g;
    int tl = idx / nseg, seg = idx % nseg;
    int r = 512 >> g;
    const float4* v = (const float4*)(V.p[g] + ((size_t)tl * r + seg * 32) * DM);
    const float4* u = (const float4*)(U.p[g] + ((size_t)tl * r + seg * 32) * DM);
    float sv = 0.f, su = 0.f;
    for (int i = threadIdx.x; i < 32 * DM / 4; i += 256) {
        float4 a = v[i]; sv += a.x * a.x + a.y * a.y + a.z * a.z + a.w * a.w;
        float4 b = u[i]; su += b.x * b.x + b.y * b.y + b.z * b.z + b.w * b.w;
    }
    sv = blk_reduce256(sv);
    su = blk_reduce256(su);
    if (threadIdx.x == 0) { g_PSQV[s] = sv; g_PSQU[s] = su; }
}

// ============== coalesced gate stats: 32 blocks x 128 rows ==============
__global__ void gstat2() {
    int tid = threadIdx.x;
    int col = tid & 127, half = tid >> 7;
    int b0 = blockIdx.x * 128;
    float sa = 0.f, cnt = 0.f;
    for (int i = 0; i < 64; i++) {
        float gg = g_GATE[(size_t)(b0 + half + 2 * i) * 128 + col];
        sa += fabsf(gg);
        cnt += (gg > 0.f) ? 1.f : 0.f;
    }
    __shared__ float s1[256], s2[256];
    s1[tid] = sa; s2[tid] = cnt;
    __syncthreads();
    if (half == 0) {
        g_PSABS[blockIdx.x * 128 + col] = s1[tid] + s1[tid + 128];
        g_PCNT[blockIdx.x * 128 + col]  = s2[tid] + s2[tid + 128];
    }
}

__global__ void finalize_kernel(float* __restrict__ out) {
    int t = threadIdx.x;   // 128 threads
    float sp = 0.f, act = 0.f;
    if (t < NT) {
        int g, tl; decode_t(t, g, tl);
        int r = 512 >> g;
        int nseg = 16 >> g;
        int base = g * 64 + tl * nseg;
        float sqv = 0.f, squ = 0.f;
        for (int j = 0; j < nseg; j++) { sqv += g_PSQV[base + j]; squ += g_PSQU[base + j]; }
        float sa = 0.f, cnt = 0.f;
        for (int cck = 0; cck < 32; cck++) { sa += g_PSABS[cck * 128 + t]; cnt += g_PCNT[cck * 128 + t]; }
        float frob = sqrtf(squ * sqv) * rsqrtf((float)(DM * r));
        sp  = tanhf(sa / (float)BATCH) * frob;
        act = cnt;
    }
    __shared__ float s1[128], s2[128];
    s1[t] = sp; s2[t] = act;
    __syncthreads();
    for (int s = 64; s > 0; s >>= 1) {
        if (t < s) { s1[t] += s1[t + s]; s2[t] += s2[t + s]; }
        __syncthreads();
    }
    if (t == 0) {
        out[SP_OFF]  = s1[0];
        out[ACT_OFF] = s2[0] / (float)BATCH;
    }
}

// ============== fp16 mma.sync GEMMs (ldmatrix, wide warp tiles) ==============
// MODE 1: Yh = gate*(Xh @ Vh^T)    BM=128 BN=256, warp 64x64, 1 CTA/SM
// MODE 2: P[z] = Yh @ W2h^T        K split 4x2560, BN=256
// MODE 3: gates                    BN=128 (N=128 total)
// BK=64, 256 thr (2x4 warps), 3-stage cp.async.

template<int MODE>
__global__ void __launch_bounds__(256) gemm_mma(float* __restrict__ out) {
    extern __shared__ uint32_t sm[];
    constexpr int BN  = (MODE == 3) ? 128 : 256;
    constexpr int NTW = BN / 32;              // warp n-tiles (8-wide each)
    constexpr int WNS = BN / 4;               // warp N span
    constexpr int STB = 16384 + BN * 128;     // stage bytes (A 16KB + B)
    constexpr int ITS = (128 + BN) / 32;      // loader iterations
    const int Kdim = (MODE == 2) ? NRT : DM;
    const int NC   = (MODE == 2) ? 40 : 12;
    const __half* __restrict__ A = (MODE == 2) ? g_Yh : g_Xh;
    const __half* __restrict__ B = (MODE == 1) ? g_Vh : ((MODE == 2) ? g_W2h : g_ENCh);
    const int bm = blockIdx.y * 128;
    const int bn = blockIdx.x * BN;
    const int kb0 = (MODE == 2) ? blockIdx.z * 2560 : 0;
    const int tid = threadIdx.x;
    const int lane = tid & 31, w = tid >> 5;
    const int gq = lane >> 2, tig = lane & 3;
    const int wm = w & 1, wn = w >> 1;

    float c[4][NTW][4];
#pragma unroll
    for (int i = 0; i < 4; i++)
#pragma unroll
        for (int j = 0; j < NTW; j++)
#pragma unroll
            for (int q = 0; q < 4; q++) c[i][j][q] = 0.f;

    const uint32_t smb = smem_u32(sm);

    const int lmk = lane >> 4;                 // A k-half selector
    uint32_t rowA[4]; int swA[4];
#pragma unroll
    for (int mt = 0; mt < 4; mt++) {
        int row = wm * 64 + mt * 16 + ((lane >> 3) & 1) * 8 + (lane & 7);
        rowA[mt] = (uint32_t)(row * 128);
        swA[mt]  = row & 7;
    }
    const int lmkB = (lane >> 3) & 1;          // B k-half selector
    uint32_t rowB[NTW / 2]; int swB[NTW / 2];
#pragma unroll
    for (int j = 0; j < NTW / 2; j++) {
        int row = wn * WNS + (2 * j + (lane >> 4)) * 8 + (lane & 7);
        rowB[j] = (uint32_t)(row * 128);
        swB[j]  = row & 7;
    }

#define LOAD_STAGE(s, cidx) do { \
    uint32_t stb = smb + (uint32_t)(s) * STB; \
    int kb = kb0 + (cidx) * 64; \
    _Pragma("unroll") \
    for (int t_ = 0; t_ < ITS; t_++) { \
        int idx = tid + t_ * 256; \
        int isB = (idx >= 1024) ? 1 : 0; \
        int rem = isB ? (idx - 1024) : idx; \
        int row = rem >> 3, u = rem & 7; \
        uint32_t dst = stb + (uint32_t)(isB * 16384 + row * 128 + ((u ^ (row & 7)) << 4)); \
        const __half* src = (isB ? B + (size_t)(bn + row) * Kdim : A + (size_t)(bm + row) * Kdim) + kb + u * 8; \
        cp16(dst, src); \
    } \
    asm volatile("cp.async.commit_group;" ::: "memory"); \
} while (0)

    LOAD_STAGE(0, 0);
    LOAD_STAGE(1, 1);

    for (int i = 0; i < NC; i++) {
        asm volatile("cp.async.wait_group 1;" ::: "memory");
        __syncthreads();
        if (i + 2 < NC) {
            LOAD_STAGE((i + 2) % 3, i + 2);
        } else {
            asm volatile("cp.async.commit_group;" ::: "memory");
        }
        const uint32_t stA = smb + (uint32_t)(i % 3) * STB;
        const uint32_t stB = stA + 16384u;
#pragma unroll
        for (int ks = 0; ks < 4; ks++) {
            uint32_t a[4][4], b[NTW][2];
#pragma unroll
            for (int mt = 0; mt < 4; mt++)
                ldsm_x4(a[mt][0], a[mt][1], a[mt][2], a[mt][3],
                        stA + rowA[mt] + (uint32_t)((((2 * ks + lmk) ^ swA[mt])) << 4));
#pragma unroll
            for (int j = 0; j < NTW / 2; j++)
                ldsm_x4(b[2 * j][0], b[2 * j][1], b[2 * j + 1][0], b[2 * j + 1][1],
                        stB + rowB[j] + (uint32_t)((((2 * ks + lmkB) ^ swB[j])) << 4));
#pragma unroll
            for (int mt = 0; mt < 4; mt++)
#pragma unroll
                for (int nt = 0; nt < NTW; nt++)
                    mma_f16(c[mt][nt], a[mt], b[nt]);
        }
    }

    // epilogue: row = bm+wm*64+mt*16+gq+rr*8, col = bn+wn*WNS+nt*8+2*tig+(q&1)
    if (MODE == 1) {
#pragma unroll
        for (int mt = 0; mt < 4; mt++) {
#pragma unroll
            for (int rr = 0; rr < 2; rr++) {
                int m = bm + wm * 64 + mt * 16 + gq + rr * 8;
                const float* grow = g_GATE + (size_t)m * 128;
                __half* yrow = g_Yh + (size_t)m * NRT;
#pragma unroll
                for (int nt = 0; nt < NTW; nt++) {
                    int colg = bn + wn * WNS + nt * 8 + 2 * tig;
                    int gg = colg >> 11;
                    int t = c_tbase[gg] + ((colg & 2047) >> c_shift[gg]);
                    float gv = grow[t];
                    *(__half2*)(yrow + colg) =
                        __floats2half2_rn(c[mt][nt][rr * 2 + 0] * gv, c[mt][nt][rr * 2 + 1] * gv);
                }
            }
        }
    } else if (MODE == 2) {
        float* P = g_P + (size_t)blockIdx.z * ((size_t)BATCH * DM);
#pragma unroll
        for (int mt = 0; mt < 4; mt++) {
#pragma unroll
            for (int rr = 0; rr < 2; rr++) {
                int m = bm + wm * 64 + mt * 16 + gq + rr * 8;
                float* prow = P + (size_t)m * DM;
#pragma unroll
                for (int nt = 0; nt < NTW; nt++) {
                    int colg = bn + wn * WNS + nt * 8 + 2 * tig;
                    *(float2*)(prow + colg) =
                        make_float2(c[mt][nt][rr * 2 + 0], c[mt][nt][rr * 2 + 1]);
                }
            }
        }
    } else {
#pragma unroll
        for (int mt = 0; mt < 4; mt++) {
#pragma unroll
            for (int rr = 0; rr < 2; rr++) {
                int m = bm + wm * 64 + mt * 16 + gq + rr * 8;
#pragma unroll
                for (int nt = 0; nt < NTW; nt++) {
#pragma unroll
                    for (int e = 0; e < 2; e++) {
                        int t = wn * WNS + nt * 8 + 2 * tig + e;
                        if (t < NT) {
                            float pre = c[mt][nt][rr * 2 + e] - g_BIAS[t];
                            float gv = pre > 0.f ? pre : 0.f;
                            g_GATE[(size_t)m * 128 + t] = gv;
                            int gg, tl; decode_t(t, gg, tl);
                            out[c_goff[gg] + (size_t)m * c_n[gg] + tl] = gv;
                        }
                    }
                }
            }
        }
    }
}

__global__ void sum4_kernel(float* __restrict__ OUT) {
    size_t i = (size_t)blockIdx.x * 256 + threadIdx.x;   // < 786432
    const size_t N4 = (size_t)BATCH * DM / 4;
    const float4* p = (const float4*)g_P;
    float4 a = p[i], b = p[i + N4], c = p[i + 2 * N4], d = p[i + 3 * N4];
    ((float4*)OUT)[i] = make_float4(a.x + b.x + c.x + d.x, a.y + b.y + c.y + d.y,
                                    a.z + b.z + c.z + d.z, a.w + b.w + c.w + d.w);
}

// ============== launch ==============
extern "C" void kernel_launch(void* const* d_in, const int* in_sizes, int n_in,
                              void* d_out, int out_size) {
    (void)in_sizes; (void)n_in; (void)out_size;
    const float* x = (const float*)d_in[0];
    P5 V, U, E, Bv;
    for (int g = 0; g < 5; g++) {
        V.p[g]  = (const float*)d_in[1 + 4 * g];
        U.p[g]  = (const float*)d_in[2 + 4 * g];
        E.p[g]  = (const float*)d_in[3 + 4 * g];
        Bv.p[g] = (const float*)d_in[4 + 4 * g];
    }
    float* out = (float*)d_out;

    const int SM_BIG   = 3 * (16384 + 256 * 128);   // 147456
    const int SM_SMALL = 3 * (16384 + 128 * 128);   // 98304
    cudaFuncSetAttribute(gemm_mma<1>, cudaFuncAttributeMaxDynamicSharedMemorySize, SM_BIG);
    cudaFuncSetAttribute(gemm_mma<2>, cudaFuncAttributeMaxDynamicSharedMemorySize, SM_BIG);
    cudaFuncSetAttribute(gemm_mma<3>, cudaFuncAttributeMaxDynamicSharedMemorySize, SM_SMALL);

    prep_fused<<<7808, 256>>>(V, E, Bv);                         // 0
    rnd_x<<<3072, 256>>>(x);                                     // 1
    gemm_mma<3><<<dim3(1, BATCH / 128), 256, SM_SMALL>>>(out);   // 2: gates
    gemm_mma<1><<<dim3(NRT / 256, BATCH / 128), 256, SM_BIG>>>(out); // 3: ncu slot
    build_w2<<<dim3(1536, 5), 256>>>(U);                         // 4
    norms2<<<320, 256>>>(V, U);                                  // 5
    gstat2<<<32, 256>>>();                                       // 6
    finalize_kernel<<<1, 128>>>(out);                            // 7
    gemm_mma<2><<<dim3(DM / 256, BATCH / 128, 4), 256, SM_BIG>>>(out); // 8
    sum4_kernel<<<3072, 256>>>(out);                             // 9
}

// round 15
// speedup vs baseline: 1.0997x; 1.0997x over previous
#include <cuda_runtime.h>
#include <cuda_fp16.h>
#include <cstdint>
#include <math.h>

#define BATCH 4096
#define DM    768
#define NT    124
#define NRT   10240

__constant__ int c_shift[5] = {9, 8, 7, 6, 5};
__constant__ int c_tbase[5] = {0, 4, 12, 28, 60};
__constant__ int c_n[5]     = {4, 8, 16, 32, 64};
__constant__ unsigned long long c_goff[5] = {3145730ull, 3162114ull, 3194882ull, 3260418ull, 3391490ull};

#define SP_OFF  3145728ull
#define ACT_OFF 3145729ull

// ---- static device scratch ----
__device__ __align__(256) __half g_Xh[(size_t)BATCH * DM];
__device__ __align__(256) __half g_Vh[(size_t)NRT * DM];    // [10240][768]
__device__ __align__(256) __half g_W2h[(size_t)DM * NRT];   // [768][10240]
__device__ __align__(256) __half g_Yh[(size_t)BATCH * NRT];
__device__ __align__(256) __half g_ENCh[128 * DM];          // 124 rows + 4 zero rows
__device__ __align__(256) float g_P[5ull * BATCH * DM];
__device__ float g_BIAS[NT];
__device__ __align__(16) float g_GATE[(size_t)BATCH * 128];
__device__ float g_PSQV[320];
__device__ float g_PSQU[320];
__device__ float g_PSABS[32 * 128];
__device__ float g_PCNT[32 * 128];

struct P5 { const float* p[5]; };

__device__ __forceinline__ void decode_t(int t, int& g, int& tl) {
    if (t < 4)       { g = 0; tl = t; }
    else if (t < 12) { g = 1; tl = t - 4; }
    else if (t < 28) { g = 2; tl = t - 12; }
    else if (t < 60) { g = 3; tl = t - 28; }
    else             { g = 4; tl = t - 60; }
}

__device__ __forceinline__ float blk_reduce256(float v) {
    __shared__ float sh[256];
    int tid = threadIdx.x;
    sh[tid] = v;
    __syncthreads();
    for (int s = 128; s > 0; s >>= 1) {
        if (tid < s) sh[tid] += sh[tid + s];
        __syncthreads();
    }
    float r = sh[0];
    __syncthreads();
    return r;
}

// ---- PTX helpers (baseline sm_80+ PTX only) ----
__device__ __forceinline__ uint32_t smem_u32(const void* p) {
    uint32_t a;
    asm("{ .reg .u64 t; cvta.to.shared.u64 t, %1; cvt.u32.u64 %0, t; }" : "=r"(a) : "l"(p));
    return a;
}
__device__ __forceinline__ void cp16(uint32_t dst, const void* src) {
    asm volatile("cp.async.cg.shared.global [%0], [%1], 16;" :: "r"(dst), "l"(src) : "memory");
}
__device__ __forceinline__ void mma_f16(float* d, const uint32_t* a, const uint32_t* b) {
    asm volatile("mma.sync.aligned.m16n8k16.row.col.f32.f16.f16.f32 "
        "{%0,%1,%2,%3}, {%4,%5,%6,%7}, {%8,%9}, {%0,%1,%2,%3};"
        : "+f"(d[0]), "+f"(d[1]), "+f"(d[2]), "+f"(d[3])
        : "r"(a[0]), "r"(a[1]), "r"(a[2]), "r"(a[3]), "r"(b[0]), "r"(b[1]));
}
__device__ __forceinline__ void ldsm_x4(uint32_t& r0, uint32_t& r1, uint32_t& r2, uint32_t& r3,
                                        uint32_t addr) {
    asm volatile("ldmatrix.sync.aligned.m8n8.x4.shared.b16 {%0,%1,%2,%3}, [%4];"
        : "=r"(r0), "=r"(r1), "=r"(r2), "=r"(r3) : "r"(addr));
}

// ============== prep kernels ==============
__global__ void prep_fused(P5 V, P5 E, P5 Bv) {
    int b = blockIdx.x;
    if (b < 7680) {
        int i4 = b * 256 + threadIdx.x;                // < 1966080
        int n = i4 / 192, kq = i4 % 192;
        int g = n >> 11, lr = n & 2047;
        float4 v = ((const float4*)V.p[g])[(size_t)lr * 192 + kq];
        __half2 h0 = __floats2half2_rn(v.x, v.y);
        __half2 h1 = __floats2half2_rn(v.z, v.w);
        uint2 r; r.x = *(uint32_t*)&h0; r.y = *(uint32_t*)&h1;
        ((uint2*)g_Vh)[(size_t)n * 192 + kq] = r;
    } else {
        int t = b - 7680;                              // 0..127
        if (t < NT) {
            int g, tl; decode_t(t, g, tl);
            const float* src = E.p[g] + (size_t)tl * DM;
            for (int i = threadIdx.x; i < DM; i += blockDim.x)
                g_ENCh[t * DM + i] = __float2half_rn(src[i]);
            if (threadIdx.x == 0) g_BIAS[t] = Bv.p[g][tl];
        } else {
            for (int i = threadIdx.x; i < DM; i += blockDim.x)
                g_ENCh[t * DM + i] = __float2half_rn(0.f);
        }
    }
}

__global__ void rnd_x(const float* __restrict__ X) {
    int i4 = blockIdx.x * 256 + threadIdx.x;           // < 786432
    float4 v = ((const float4*)X)[i4];
    __half2 h0 = __floats2half2_rn(v.x, v.y);
    __half2 h1 = __floats2half2_rn(v.z, v.w);
    uint2 r; r.x = *(uint32_t*)&h0; r.y = *(uint32_t*)&h1;
    ((uint2*)g_Xh)[i4] = r;
}

__global__ void build_w2(P5 U) {
    int g = blockIdx.y;
    int r = 512 >> g;
    int rq = r >> 2;
    int i4 = blockIdx.x * 256 + threadIdx.x;           // < 393216 per group
    int t = i4 / (DM * rq);
    int rem = i4 % (DM * rq);
    int d = rem / rq, jq = rem % rq;
    float4 v = ((const float4*)U.p[g])[(size_t)(t * DM + d) * rq + jq];
    __half2 h0 = __floats2half2_rn(v.x, v.y);
    __half2 h1 = __floats2half2_rn(v.z, v.w);
    uint2 rv; rv.x = *(uint32_t*)&h0; rv.y = *(uint32_t*)&h1;
    ((uint2*)g_W2h)[(size_t)d * 2560 + (g << 9) + t * rq + jq] = rv;
}

// ============== balanced norms: 320 segments of 32 rows ==============
__global__ void norms2(P5 V, P5 U) {
    int s = blockIdx.x;                   // 0..319
    int g = s >> 6, idx = s & 63;
    int nseg = 16 >> g;
    int tl = idx / nseg, seg = idx % nseg;
    int r = 512 >> g;
    const float4* v = (const float4*)(V.p[g] + ((size_t)tl * r + seg * 32) * DM);
    const float4* u = (const float4*)(U.p[g] + ((size_t)tl * r + seg * 32) * DM);
    float sv = 0.f, su = 0.f;
    for (int i = threadIdx.x; i < 32 * DM / 4; i += 256) {
        float4 a = v[i]; sv += a.x * a.x + a.y * a.y + a.z * a.z + a.w * a.w;
        float4 b = u[i]; su += b.x * b.x + b.y * b.y + b.z * b.z + b.w * b.w;
    }
    sv = blk_reduce256(sv);
    su = blk_reduce256(su);
    if (threadIdx.x == 0) { g_PSQV[s] = sv; g_PSQU[s] = su; }
}

// ============== coalesced gate stats: 32 blocks x 128 rows ==============
__global__ void gstat2() {
    int tid = threadIdx.x;
    int col = tid & 127, half = tid >> 7;
    int b0 = blockIdx.x * 128;
    float sa = 0.f, cnt = 0.f;
    for (int i = 0; i < 64; i++) {
        float gg = g_GATE[(size_t)(b0 + half + 2 * i) * 128 + col];
        sa += fabsf(gg);
        cnt += (gg > 0.f) ? 1.f : 0.f;
    }
    __shared__ float s1[256], s2[256];
    s1[tid] = sa; s2[tid] = cnt;
    __syncthreads();
    if (half == 0) {
        g_PSABS[blockIdx.x * 128 + col] = s1[tid] + s1[tid + 128];
        g_PCNT[blockIdx.x * 128 + col]  = s2[tid] + s2[tid + 128];
    }
}

__global__ void finalize_kernel(float* __restrict__ out) {
    int t = threadIdx.x;   // 128 threads
    float sp = 0.f, act = 0.f;
    if (t < NT) {
        int g, tl; decode_t(t, g, tl);
        int r = 512 >> g;
        int nseg = 16 >> g;
        int base = g * 64 + tl * nseg;
        float sqv = 0.f, squ = 0.f;
        for (int j = 0; j < nseg; j++) { sqv += g_PSQV[base + j]; squ += g_PSQU[base + j]; }
        float sa = 0.f, cnt = 0.f;
        for (int cck = 0; cck < 32; cck++) { sa += g_PSABS[cck * 128 + t]; cnt += g_PCNT[cck * 128 + t]; }
        float frob = sqrtf(squ * sqv) * rsqrtf((float)(DM * r));
        sp  = tanhf(sa / (float)BATCH) * frob;
        act = cnt;
    }
    __shared__ float s1[128], s2[128];
    s1[t] = sp; s2[t] = act;
    __syncthreads();
    for (int s = 64; s > 0; s >>= 1) {
        if (t < s) { s1[t] += s1[t + s]; s2[t] += s2[t + s]; }
        __syncthreads();
    }
    if (t == 0) {
        out[SP_OFF]  = s1[0];
        out[ACT_OFF] = s2[0] / (float)BATCH;
    }
}

// ============== fp16 mma.sync GEMMs (ldmatrix, double-buffered frags) ==============
// MODE 1: Yh = gate*(Xh @ Vh^T)   M=4096 N=10240 K=768
// MODE 2: P[z] = Yh @ W2h^T       K split 5x2048
// MODE 3: gates
// BM=BN=128, BK=64, 256 thr, warp 64x32 (4x4 m16n8k16), 3-stage cp.async, 2 CTA/SM.
#define STGW 8192                 // 32-bit words per stage = 32KB
#define SMEMSZ (3 * STGW * 4)     // 96 KB

template<int MODE>
__global__ void __launch_bounds__(256, 2) gemm_mma(float* __restrict__ out) {
    extern __shared__ uint32_t sm[];
    const int Kdim = (MODE == 2) ? NRT : DM;
    const int NC   = (MODE == 2) ? 32 : 12;
    const __half* __restrict__ A = (MODE == 2) ? g_Yh : g_Xh;
    const __half* __restrict__ B = (MODE == 1) ? g_Vh : ((MODE == 2) ? g_W2h : g_ENCh);
    const int bm = blockIdx.y * 128;
    const int bn = blockIdx.x * 128;
    const int kb0 = (MODE == 2) ? blockIdx.z * 2048 : 0;
    const int tid = threadIdx.x;
    const int lane = tid & 31, w = tid >> 5;
    const int gq = lane >> 2, tig = lane & 3;
    const int wm = w & 1, wn = w >> 1;

    float c[4][4][4];
#pragma unroll
    for (int i = 0; i < 4; i++)
#pragma unroll
        for (int j = 0; j < 4; j++)
#pragma unroll
            for (int q = 0; q < 4; q++) c[i][j][q] = 0.f;

    const uint32_t smb = smem_u32(sm);

    const int lmk = lane >> 4;                 // A k-half selector
    uint32_t rowA[4]; int swA[4];
#pragma unroll
    for (int mt = 0; mt < 4; mt++) {
        int row = wm * 64 + mt * 16 + ((lane >> 3) & 1) * 8 + (lane & 7);
        rowA[mt] = (uint32_t)(row * 128);
        swA[mt]  = row & 7;
    }
    const int lmkB = (lane >> 3) & 1;          // B k-half selector
    uint32_t rowB[2]; int swB[2];
#pragma unroll
    for (int j = 0; j < 2; j++) {
        int row = wn * 32 + (2 * j + (lane >> 4)) * 8 + (lane & 7);
        rowB[j] = (uint32_t)(row * 128);
        swB[j]  = row & 7;
    }

#define LOAD_STAGE(s, cidx) do { \
    uint32_t stb = smb + (uint32_t)(s) * (STGW * 4); \
    int kb = kb0 + (cidx) * 64; \
    _Pragma("unroll") \
    for (int t_ = 0; t_ < 8; t_++) { \
        int idx = tid + t_ * 256; \
        int isB = idx >> 10, rem = idx & 1023; \
        int row = rem >> 3, u = rem & 7; \
        uint32_t dst = stb + (uint32_t)(isB * 16384 + row * 128 + ((u ^ (row & 7)) << 4)); \
        const __half* src = (isB ? B + (size_t)(bn + row) * Kdim : A + (size_t)(bm + row) * Kdim) + kb + u * 8; \
        cp16(dst, src); \
    } \
    asm volatile("cp.async.commit_group;" ::: "memory"); \
} while (0)

#define LDFRAG(buf, ks) do { \
    _Pragma("unroll") \
    for (int mt = 0; mt < 4; mt++) \
        ldsm_x4(a[buf][mt][0], a[buf][mt][1], a[buf][mt][2], a[buf][mt][3], \
                stA + rowA[mt] + (uint32_t)((((2 * (ks) + lmk) ^ swA[mt])) << 4)); \
    _Pragma("unroll") \
    for (int j = 0; j < 2; j++) \
        ldsm_x4(b[buf][2 * j][0], b[buf][2 * j][1], b[buf][2 * j + 1][0], b[buf][2 * j + 1][1], \
                stB + rowB[j] + (uint32_t)((((2 * (ks) + lmkB) ^ swB[j])) << 4)); \
} while (0)

    LOAD_STAGE(0, 0);
    LOAD_STAGE(1, 1);

    for (int i = 0; i < NC; i++) {
        asm volatile("cp.async.wait_group 1;" ::: "memory");
        __syncthreads();
        const uint32_t stA = smb + (uint32_t)(i % 3) * (STGW * 4);
        const uint32_t stB = stA + 16384u;
        uint32_t a[2][4][4], b[2][4][2];
        LDFRAG(0, 0);
        if (i + 2 < NC) {
            LOAD_STAGE((i + 2) % 3, i + 2);
        } else {
            asm volatile("cp.async.commit_group;" ::: "memory");
        }
#pragma unroll
        for (int ks = 0; ks < 4; ks++) {
            if (ks < 3) LDFRAG((ks + 1) & 1, ks + 1);
            const int cur = ks & 1;
#pragma unroll
            for (int mt = 0; mt < 4; mt++)
#pragma unroll
                for (int nt = 0; nt < 4; nt++)
                    mma_f16(c[mt][nt], a[cur][mt], b[cur][nt]);
        }
    }

    // epilogue: c[mt][nt][q] -> row = bm+wm*64+mt*16+gq+(q>>1)*8, col = bn+wn*32+nt*8+2*tig+(q&1)
    if (MODE == 1) {
#pragma unroll
        for (int mt = 0; mt < 4; mt++) {
#pragma unroll
            for (int rr = 0; rr < 2; rr++) {
                int m = bm + wm * 64 + mt * 16 + gq + rr * 8;
                const float* grow = g_GATE + (size_t)m * 128;
                __half* yrow = g_Yh + (size_t)m * NRT;
#pragma unroll
                for (int nt = 0; nt < 4; nt++) {
                    int colg = bn + wn * 32 + nt * 8 + 2 * tig;
                    int gg = colg >> 11;
                    int t = c_tbase[gg] + ((colg & 2047) >> c_shift[gg]);
                    float gv = grow[t];
                    *(__half2*)(yrow + colg) =
                        __floats2half2_rn(c[mt][nt][rr * 2 + 0] * gv, c[mt][nt][rr * 2 + 1] * gv);
                }
            }
        }
    } else if (MODE == 2) {
        float* P = g_P + (size_t)blockIdx.z * ((size_t)BATCH * DM);
#pragma unroll
        for (int mt = 0; mt < 4; mt++) {
#pragma unroll
            for (int rr = 0; rr < 2; rr++) {
                int m = bm + wm * 64 + mt * 16 + gq + rr * 8;
                float* prow = P + (size_t)m * DM;
#pragma unroll
                for (int nt = 0; nt < 4; nt++) {
                    int colg = bn + wn * 32 + nt * 8 + 2 * tig;
                    *(float2*)(prow + colg) =
                        make_float2(c[mt][nt][rr * 2 + 0], c[mt][nt][rr * 2 + 1]);
                }
            }
        }
    } else {
#pragma unroll
        for (int mt = 0; mt < 4; mt++) {
#pragma unroll
            for (int rr = 0; rr < 2; rr++) {
                int m = bm + wm * 64 + mt * 16 + gq + rr * 8;
#pragma unroll
                for (int nt = 0; nt < 4; nt++) {
#pragma unroll
                    for (int e = 0; e < 2; e++) {
                        int t = wn * 32 + nt * 8 + 2 * tig + e;
                        if (t < NT) {
                            float pre = c[mt][nt][rr * 2 + e] - g_BIAS[t];
                            float gv = pre > 0.f ? pre : 0.f;
                            g_GATE[(size_t)m * 128 + t] = gv;
                            int gg, tl; decode_t(t, gg, tl);
                            out[c_goff[gg] + (size_t)m * c_n[gg] + tl] = gv;
                        }
                    }
                }
            }
        }
    }
}

__global__ void sum5_kernel(float* __restrict__ OUT) {
    size_t i = (size_t)blockIdx.x * 256 + threadIdx.x;   // < 786432
    const size_t N4 = (size_t)BATCH * DM / 4;
    const float4* p = (const float4*)g_P;
    float4 a = p[i], b = p[i + N4], c = p[i + 2 * N4], d = p[i + 3 * N4], e = p[i + 4 * N4];
    ((float4*)OUT)[i] = make_float4(a.x + b.x + c.x + d.x + e.x, a.y + b.y + c.y + d.y + e.y,
                                    a.z + b.z + c.z + d.z + e.z, a.w + b.w + c.w + d.w + e.w);
}

// ============== launch ==============
extern "C" void kernel_launch(void* const* d_in, const int* in_sizes, int n_in,
                              void* d_out, int out_size) {
    (void)in_sizes; (void)n_in; (void)out_size;
    const float* x = (const float*)d_in[0];
    P5 V, U, E, Bv;
    for (int g = 0; g < 5; g++) {
        V.p[g]  = (const float*)d_in[1 + 4 * g];
        U.p[g]  = (const float*)d_in[2 + 4 * g];
        E.p[g]  = (const float*)d_in[3 + 4 * g];
        Bv.p[g] = (const float*)d_in[4 + 4 * g];
    }
    float* out = (float*)d_out;

    cudaFuncSetAttribute(gemm_mma<1>, cudaFuncAttributeMaxDynamicSharedMemorySize, SMEMSZ);
    cudaFuncSetAttribute(gemm_mma<2>, cudaFuncAttributeMaxDynamicSharedMemorySize, SMEMSZ);
    cudaFuncSetAttribute(gemm_mma<3>, cudaFuncAttributeMaxDynamicSharedMemorySize, SMEMSZ);

    // side stream (built-in per-thread stream; no stream creation needed)
    cudaStream_t s1 = cudaStreamPerThread;
    cudaEvent_t evFork, evGates, evSide;
    cudaEventCreateWithFlags(&evFork,  cudaEventDisableTiming);
    cudaEventCreateWithFlags(&evGates, cudaEventDisableTiming);
    cudaEventCreateWithFlags(&evSide,  cudaEventDisableTiming);

    cudaEventRecord(evFork, 0);
    cudaStreamWaitEvent(s1, evFork, 0);

    rnd_x<<<3072, 256>>>(x);                                     // 0
    prep_fused<<<7808, 256>>>(V, E, Bv);                         // 1
    gemm_mma<3><<<dim3(1, BATCH / 128), 256, SMEMSZ>>>(out);     // 2: gates
    cudaEventRecord(evGates, 0);
    gemm_mma<1><<<dim3(NRT / 128, BATCH / 128), 256, SMEMSZ>>>(out); // 3: ncu slot

    // side stream: U prep + norms + gate stats overlap gemm1
    build_w2<<<dim3(1536, 5), 256, 0, s1>>>(U);                  // 4
    norms2<<<320, 256, 0, s1>>>(V, U);                           // 5
    cudaStreamWaitEvent(s1, evGates, 0);
    gstat2<<<32, 256, 0, s1>>>();                                // 6
    cudaEventRecord(evSide, s1);

    cudaStreamWaitEvent(0, evSide, 0);
    finalize_kernel<<<1, 128>>>(out);                            // 7
    gemm_mma<2><<<dim3(DM / 128, BATCH / 128, 5), 256, SMEMSZ>>>(out); // 8
    sum5_kernel<<<3072, 256>>>(out);                             // 9
}